// round 6
// baseline (speedup 1.0000x reference)
#include <cuda_runtime.h>
#include <cstdint>
#include <math.h>

#define V_SZ 100000
#define H_SZ 300
#define HP   304          // padded K (pads zero-weighted + zero-filled)
#define B_SZ 64
#define L_SZ 64
#define NBLK_LOG 391      // 391*256 = 100096 >= V_SZ
#define KCH 12            // logits K chunk (300 = 25*12)
#define NCHUNK 25

typedef unsigned long long ull;

// ---------------- device scratch ----------------
__device__ __align__(16) float g_h[2][HP * B_SZ];           // hidden, [k][b]
__device__ __align__(16) float g_xT[HP * B_SZ];             // decoder input
__device__ __align__(16) float g_xT_all[L_SZ * HP * B_SZ];  // encoder embeds
__device__ ull g_part[NBLK_LOG * B_SZ];

// ---------------- helpers ----------------
static __device__ __forceinline__ ull pk2(float lo, float hi) {
    ull r; asm("mov.b64 %0, {%1, %2};" : "=l"(r) : "f"(lo), "f"(hi)); return r;
}
static __device__ __forceinline__ void ffma2(ull& d, ull a, ull b) {
    asm("fma.rn.f32x2 %0, %1, %2, %0;" : "+l"(d) : "l"(a), "l"(b));
}
static __device__ __forceinline__ float2 upk2(ull v) {
    float2 r; asm("mov.b64 {%0, %1}, %2;" : "=f"(r.x), "=f"(r.y) : "l"(v)); return r;
}
static __device__ __forceinline__ unsigned ordf(float f) {
    unsigned u = __float_as_uint(f);
    return (u & 0x80000000u) ? ~u : (u | 0x80000000u);
}
static __device__ __forceinline__ ull umax64(ull a, ull b) { return a > b ? a : b; }
static __device__ __forceinline__ unsigned s2u(const void* p) {
    return (unsigned)__cvta_generic_to_shared(p);
}
#define CP16(dst, src) asm volatile("cp.async.cg.shared.global [%0], [%1], 16;" :: "r"(dst), "l"(src))

// cheap double exp (Cody-Waite + deg-9), rel err ~7e-12
static __device__ __forceinline__ double dexp_(double x) {
    const double L2E   = 1.4426950408889634074;
    const double LN2HI = 6.93147180369123816490e-01;
    const double LN2LO = 1.90821492927058770002e-10;
    int n = __double2int_rn(x * L2E);
    double nd = (double)n;
    double r = fma(-nd, LN2HI, x);
    r = fma(-nd, LN2LO, r);
    double p = 2.7557319223985893e-6;
    p = fma(p, r, 2.4801587301587302e-5);
    p = fma(p, r, 1.9841269841269841e-4);
    p = fma(p, r, 1.3888888888888889e-3);
    p = fma(p, r, 8.3333333333333333e-3);
    p = fma(p, r, 4.1666666666666667e-2);
    p = fma(p, r, 1.6666666666666667e-1);
    p = fma(p, r, 0.5);
    p = fma(p, r, 1.0);
    p = fma(p, r, 1.0);
    return p * __longlong_as_double((long long)((ull)(1023 + n) << 52));
}
static __device__ __forceinline__ float sigd(float x) {
    double xd = (double)fminf(fmaxf(x, -30.0f), 30.0f);
    double e = dexp_(-xd);
    double den = 1.0 + e;
    double r0 = (double)(1.0f / (float)den);
    r0 = r0 * fma(-den, r0, 2.0);
    return (float)r0;
}
static __device__ __forceinline__ float tanhd(float x) {
    double xd = (double)fminf(fmaxf(x, -30.0f), 30.0f);
    double e = dexp_(-2.0 * xd);
    double den = 1.0 + e;
    double r0 = (double)(1.0f / (float)den);
    r0 = r0 * fma(-den, r0, 2.0);
    return (float)fma(-2.0 * e, r0, 1.0);
}

// ---------------- init ----------------
__global__ void k_init(const float* __restrict__ emb) {
    int i = blockIdx.x * 256 + threadIdx.x;    // 76*256 = HP*64 exact
    int k = i >> 6;
    g_h[0][i] = 0.0f;
    g_h[1][i] = 0.0f;
    g_xT[i] = (k < H_SZ) ? fmaxf(emb[k], 0.0f) : 0.0f;
}

// ---------------- gather encoder embeddings (+ zero pads) ----------------
__global__ void k_gather_enc(const int* __restrict__ input, const float* __restrict__ emb) {
    __shared__ int ids[B_SZ];
    int t = blockIdx.x, tid = threadIdx.x;
    if (tid < B_SZ) ids[tid] = input[t * B_SZ + tid];
    __syncthreads();
    for (int i = tid; i < B_SZ * H_SZ; i += 256) {
        int b = i / H_SZ, k = i - b * H_SZ;
        g_xT_all[((size_t)t * HP + k) * B_SZ + b] = emb[(size_t)ids[b] * H_SZ + k];
    }
    g_xT_all[((size_t)t * HP + H_SZ) * B_SZ + tid] = 0.0f;   // pads k=300..303
}

// ---------------- GRU step: grid 100 (3 n/block), block 512 --------------
__global__ __launch_bounds__(512) void k_gru(
    const float* __restrict__ W_ih, const float* __restrict__ W_hh,
    const float* __restrict__ b_ih, const float* __restrict__ b_hh,
    int xoff, int hin, int hout)
{
    __shared__ __align__(16) char smraw[36864];
    float (*Ws)[HP] = (float(*)[HP])smraw;    // [18][304] during main loop
    ull* Red = (ull*)smraw;                   // [8][18][32] ull after (union)

    int tid = threadIdx.x;
    int n0 = blockIdx.x * 3;
    int w = tid >> 5, lane = tid & 31;

    for (int i = tid; i < 18 * 75; i += 512) {
        int row = i / 75, q = i - row * 75;
        int rr = (row < 9) ? row : row - 9;
        int g = rr / 3, nl = rr - g * 3;
        const float* src = ((row < 9) ? W_ih : W_hh) + (size_t)(g * H_SZ + n0 + nl) * H_SZ;
        *(float4*)&Ws[row][q * 4] = *(const float4*)(src + q * 4);
    }
    if (tid < 18) { float4 z = {0.f, 0.f, 0.f, 0.f}; *(float4*)&Ws[tid][300] = z; }
    __syncthreads();

    const float* xp = (xoff >= 0) ? (g_xT_all + xoff) : g_xT;
    const float* hp = g_h[hin];
    int ks = w * 19;

    ull a[18];
#pragma unroll
    for (int r = 0; r < 18; r++) a[r] = 0ull;

#pragma unroll 4
    for (int k = ks; k < ks + 19; k++) {
        ull xq = *(const ull*)(xp + k * 64 + lane * 2);
        ull hq = *(const ull*)(hp + k * 64 + lane * 2);
#pragma unroll
        for (int r = 0; r < 9; r++) ffma2(a[r], pk2(Ws[r][k], Ws[r][k]), xq);
#pragma unroll
        for (int r = 9; r < 18; r++) ffma2(a[r], pk2(Ws[r][k], Ws[r][k]), hq);
    }
    __syncthreads();

    if (w >= 8) {
#pragma unroll
        for (int r = 0; r < 18; r++) Red[((w - 8) * 18 + r) * 32 + lane] = a[r];
    }
    __syncthreads();
    if (w < 8) {
#pragma unroll
        for (int r = 0; r < 18; r++) {
            ull o = Red[(w * 18 + r) * 32 + lane];
            float2 pa = upk2(a[r]), po = upk2(o);
            Red[(w * 18 + r) * 32 + lane] = pk2(pa.x + po.x, pa.y + po.y);
        }
    }
    __syncthreads();

    if (tid < 192) {
        int nl = tid >> 6, b = tid & 63;
        const float* Redf = (const float*)Red;
        float sir = 0, siz = 0, sin_ = 0, shr = 0, shz = 0, shn = 0;
#pragma unroll
        for (int s2 = 0; s2 < 8; s2++) {
            const float* base = Redf + s2 * 1152;
            sir  += base[nl * 64 + b];
            siz  += base[(3 + nl) * 64 + b];
            sin_ += base[(6 + nl) * 64 + b];
            shr  += base[(9 + nl) * 64 + b];
            shz  += base[(12 + nl) * 64 + b];
            shn  += base[(15 + nl) * 64 + b];
        }
        int n = n0 + nl;
        float r = sigd(sir + b_ih[n] + shr + b_hh[n]);
        float z = sigd(siz + b_ih[H_SZ + n] + shz + b_hh[H_SZ + n]);
        float nn = tanhd(sin_ + b_ih[2 * H_SZ + n] + r * (shn + b_hh[2 * H_SZ + n]));
        float hold = hp[n * 64 + b];
        g_h[hout][n * 64 + b] = (1.0f - z) * nn + z * hold;
    }
}

// ---------------- logits GEMM + fused per-block argmax -------------------
// grid 391, block 256. vy = tid>>3 (32 groups x 8 vocab rows), bx = tid&7
// (8 batches). Double-buffered cp.async; W LDS once per kk4 (both halves).
// Per-buffer layout: Wt 256 rows x 12 floats + 16B skew per 8 rows (12800B),
// hs [12][64] (3072B)  -> 15872B per buffer, 2 buffers.
__global__ __launch_bounds__(256) void k_logits(
    int hin, const float* __restrict__ W, const float* __restrict__ bias)
{
    __shared__ __align__(16) char sm[2][15872];

    int tid = threadIdx.x, blk = blockIdx.x;
    int v0 = blk * 256;
    int vy = tid >> 3, bx = tid & 7;
    const float* hT = g_h[hin];

    ull acc[8][4];
#pragma unroll
    for (int i = 0; i < 8; i++)
#pragma unroll
        for (int j = 0; j < 4; j++) acc[i][j] = 0ull;

    // ---- staging lambda: chunk c into buffer buf ----
    auto stage = [&](int c, int buf) {
        float* Wt = (float*)sm[buf];
        float* hs = (float*)(sm[buf] + 12800);
        int k0 = c * KCH;
#pragma unroll
        for (int i = tid; i < 768; i += 256) {          // 256 rows x 3 float4
            int vl = i / 3, q = i - vl * 3;
            int rv = v0 + vl; if (rv > V_SZ - 1) rv = V_SZ - 1;
            unsigned dst = s2u(Wt + vl * 12 + (vl >> 3) * 4 + q * 4);
            CP16(dst, W + (size_t)rv * H_SZ + k0 + q * 4);
        }
        if (tid < 192) CP16(s2u(hs + tid * 4), hT + k0 * 64 + tid * 4);
        asm volatile("cp.async.commit_group;");
    };

    stage(0, 0);
    for (int c = 0; c < NCHUNK; c++) {
        if (c + 1 < NCHUNK) stage(c + 1, (c + 1) & 1);
        if (c + 1 < NCHUNK) asm volatile("cp.async.wait_group 1;");
        else                asm volatile("cp.async.wait_group 0;");
        __syncthreads();

        const float* Wt = (const float*)sm[c & 1];
        const float* hs = (const float*)(sm[c & 1] + 12800);
        const float* wbase = Wt + vy * 100;             // vy*8 rows *12 + vy*4 skew
#pragma unroll
        for (int kk = 0; kk < KCH; kk += 4) {
            ulonglong2 hA0 = *(const ulonglong2*)(hs + (kk + 0) * 64 + bx * 8);
            ulonglong2 hB0 = *(const ulonglong2*)(hs + (kk + 0) * 64 + bx * 8 + 4);
            ulonglong2 hA1 = *(const ulonglong2*)(hs + (kk + 1) * 64 + bx * 8);
            ulonglong2 hB1 = *(const ulonglong2*)(hs + (kk + 1) * 64 + bx * 8 + 4);
            ulonglong2 hA2 = *(const ulonglong2*)(hs + (kk + 2) * 64 + bx * 8);
            ulonglong2 hB2 = *(const ulonglong2*)(hs + (kk + 2) * 64 + bx * 8 + 4);
            ulonglong2 hA3 = *(const ulonglong2*)(hs + (kk + 3) * 64 + bx * 8);
            ulonglong2 hB3 = *(const ulonglong2*)(hs + (kk + 3) * 64 + bx * 8 + 4);
#pragma unroll
            for (int iv = 0; iv < 8; iv++) {
                float4 wv = *(const float4*)(wbase + iv * 12 + kk);
                ull w;
                w = pk2(wv.x, wv.x);
                ffma2(acc[iv][0], w, hA0.x); ffma2(acc[iv][1], w, hA0.y);
                ffma2(acc[iv][2], w, hB0.x); ffma2(acc[iv][3], w, hB0.y);
                w = pk2(wv.y, wv.y);
                ffma2(acc[iv][0], w, hA1.x); ffma2(acc[iv][1], w, hA1.y);
                ffma2(acc[iv][2], w, hB1.x); ffma2(acc[iv][3], w, hB1.y);
                w = pk2(wv.z, wv.z);
                ffma2(acc[iv][0], w, hA2.x); ffma2(acc[iv][1], w, hA2.y);
                ffma2(acc[iv][2], w, hB2.x); ffma2(acc[iv][3], w, hB2.y);
                w = pk2(wv.w, wv.w);
                ffma2(acc[iv][0], w, hA3.x); ffma2(acc[iv][1], w, hA3.y);
                ffma2(acc[iv][2], w, hB3.x); ffma2(acc[iv][3], w, hB3.y);
            }
        }
        __syncthreads();    // all done reading buf[c&1] before restage at c+2
    }

    // fused argmax: key = (ordered_float << 32) | ~v  (JAX first-index ties)
    ull lm[8];
#pragma unroll
    for (int j = 0; j < 8; j++) lm[j] = 0ull;
#pragma unroll
    for (int iv = 0; iv < 8; iv++) {
        int v = v0 + vy * 8 + iv;
        if (v < V_SZ) {
            float bj = bias[v];
            ull tg = (ull)(~(unsigned)v);
            float2 p0 = upk2(acc[iv][0]), p1 = upk2(acc[iv][1]);
            float2 p2 = upk2(acc[iv][2]), p3 = upk2(acc[iv][3]);
            lm[0] = umax64(lm[0], ((ull)ordf(p0.x + bj) << 32) | tg);
            lm[1] = umax64(lm[1], ((ull)ordf(p0.y + bj) << 32) | tg);
            lm[2] = umax64(lm[2], ((ull)ordf(p1.x + bj) << 32) | tg);
            lm[3] = umax64(lm[3], ((ull)ordf(p1.y + bj) << 32) | tg);
            lm[4] = umax64(lm[4], ((ull)ordf(p2.x + bj) << 32) | tg);
            lm[5] = umax64(lm[5], ((ull)ordf(p2.y + bj) << 32) | tg);
            lm[6] = umax64(lm[6], ((ull)ordf(p3.x + bj) << 32) | tg);
            lm[7] = umax64(lm[7], ((ull)ordf(p3.y + bj) << 32) | tg);
        }
    }
    ull* red = (ull*)sm;                  // [32 vy][64 b] = 16KB overlay
#pragma unroll
    for (int j = 0; j < 8; j++) red[vy * 64 + bx * 8 + j] = lm[j];
    __syncthreads();
    if (tid < B_SZ) {
        ull m = red[tid];
#pragma unroll
        for (int r = 1; r < 32; r++) m = umax64(m, red[r * 64 + tid]);
        g_part[blk * B_SZ + tid] = m;
    }
}

// ---------------- finalize ----------------
__global__ void k_finalize(const float* __restrict__ emb, float* __restrict__ out, int t) {
    __shared__ ull sred[256];
    __shared__ int sid;
    int b = blockIdx.x, tid = threadIdx.x;
    ull m = 0;
    for (int i = tid; i < NBLK_LOG; i += 256) m = umax64(m, g_part[i * B_SZ + b]);
    sred[tid] = m;
    __syncthreads();
    for (int s = 128; s > 0; s >>= 1) {
        if (tid < s) sred[tid] = umax64(sred[tid], sred[tid + s]);
        __syncthreads();
    }
    if (tid == 0) {
        unsigned id = ~(unsigned)(sred[0] & 0xffffffffull);
        sid = (int)id;
        out[t * B_SZ + b] = (float)id;
    }
    __syncthreads();
    int id = sid;
    for (int k = tid; k < H_SZ; k += 256)
        g_xT[k * 64 + b] = fmaxf(emb[(size_t)id * H_SZ + k], 0.0f);
}

// ---------------- launch ----------------
extern "C" void kernel_launch(void* const* d_in, const int* in_sizes, int n_in,
                              void* d_out, int out_size) {
    const int*   input = (const int*)d_in[0];
    const float* emb   = (const float*)d_in[1];
    const float* eWih  = (const float*)d_in[2];
    const float* eWhh  = (const float*)d_in[3];
    const float* ebih  = (const float*)d_in[4];
    const float* ebhh  = (const float*)d_in[5];
    const float* dWih  = (const float*)d_in[6];
    const float* dWhh  = (const float*)d_in[7];
    const float* dbih  = (const float*)d_in[8];
    const float* dbhh  = (const float*)d_in[9];
    const float* oW    = (const float*)d_in[10];
    const float* ob    = (const float*)d_in[11];
    float* out = (float*)d_out;

    k_init<<<76, 256>>>(emb);
    k_gather_enc<<<L_SZ, 256>>>(input, emb);

    for (int t = 0; t < L_SZ; t++)
        k_gru<<<100, 512>>>(eWih, eWhh, ebih, ebhh, t * HP * B_SZ, t & 1, (t + 1) & 1);

    int p = 0;
    for (int t = 0; t < L_SZ; t++) {
        k_gru<<<100, 512>>>(dWih, dWhh, dbih, dbhh, -1, p, 1 - p);
        k_logits<<<NBLK_LOG, 256>>>(1 - p, oW, ob);
        k_finalize<<<B_SZ, 256>>>(emb, out, t);
        p = 1 - p;
    }
}

// round 7
// speedup vs baseline: 1.9787x; 1.9787x over previous
#include <cuda_runtime.h>
#include <cstdint>
#include <math.h>

#define V_SZ 100000
#define H_SZ 300
#define HP   304          // padded K (pads zero-weighted + zero-filled)
#define B_SZ 64
#define L_SZ 64
#define NBLK_LOG 391      // 391*256 = 100096 >= V_SZ
#define KCH 20            // logits K chunk (300 = 15*20)
#define NCHUNK 15
#define ENC_GRID 100

typedef unsigned long long ull;

// ---------------- device scratch ----------------
__device__ __align__(16) float g_h[2][HP * B_SZ];           // hidden, [k][b]
__device__ __align__(16) float g_xT[HP * B_SZ];             // decoder input
__device__ __align__(16) float g_xT_all[L_SZ * HP * B_SZ];  // encoder embeds
__device__ ull g_part[NBLK_LOG * B_SZ];
__device__ unsigned g_bar;                                  // encoder grid barrier

// ---------------- helpers ----------------
static __device__ __forceinline__ ull pk2(float lo, float hi) {
    ull r; asm("mov.b64 %0, {%1, %2};" : "=l"(r) : "f"(lo), "f"(hi)); return r;
}
static __device__ __forceinline__ void ffma2(ull& d, ull a, ull b) {
    asm("fma.rn.f32x2 %0, %1, %2, %0;" : "+l"(d) : "l"(a), "l"(b));
}
static __device__ __forceinline__ float2 upk2(ull v) {
    float2 r; asm("mov.b64 {%0, %1}, %2;" : "=f"(r.x), "=f"(r.y) : "l"(v)); return r;
}
static __device__ __forceinline__ unsigned ordf(float f) {
    unsigned u = __float_as_uint(f);
    return (u & 0x80000000u) ? ~u : (u | 0x80000000u);
}
static __device__ __forceinline__ ull umax64(ull a, ull b) { return a > b ? a : b; }
static __device__ __forceinline__ unsigned s2u(const void* p) {
    return (unsigned)__cvta_generic_to_shared(p);
}
#define CP16(dst, src) asm volatile("cp.async.cg.shared.global [%0], [%1], 16;" :: "r"(dst), "l"(src))

// cheap double exp (Cody-Waite + deg-9), rel err ~7e-12
static __device__ __forceinline__ double dexp_(double x) {
    const double L2E   = 1.4426950408889634074;
    const double LN2HI = 6.93147180369123816490e-01;
    const double LN2LO = 1.90821492927058770002e-10;
    int n = __double2int_rn(x * L2E);
    double nd = (double)n;
    double r = fma(-nd, LN2HI, x);
    r = fma(-nd, LN2LO, r);
    double p = 2.7557319223985893e-6;
    p = fma(p, r, 2.4801587301587302e-5);
    p = fma(p, r, 1.9841269841269841e-4);
    p = fma(p, r, 1.3888888888888889e-3);
    p = fma(p, r, 8.3333333333333333e-3);
    p = fma(p, r, 4.1666666666666667e-2);
    p = fma(p, r, 1.6666666666666667e-1);
    p = fma(p, r, 0.5);
    p = fma(p, r, 1.0);
    p = fma(p, r, 1.0);
    return p * __longlong_as_double((long long)((ull)(1023 + n) << 52));
}
static __device__ __forceinline__ float sigd(float x) {
    double xd = (double)fminf(fmaxf(x, -30.0f), 30.0f);
    double e = dexp_(-xd);
    double den = 1.0 + e;
    double r0 = (double)(1.0f / (float)den);
    r0 = r0 * fma(-den, r0, 2.0);
    return (float)r0;
}
static __device__ __forceinline__ float tanhd(float x) {
    double xd = (double)fminf(fmaxf(x, -30.0f), 30.0f);
    double e = dexp_(-2.0 * xd);
    double den = 1.0 + e;
    double r0 = (double)(1.0f / (float)den);
    r0 = r0 * fma(-den, r0, 2.0);
    return (float)fma(-2.0 * e, r0, 1.0);
}

// ---------------- init ----------------
__global__ void k_init(const float* __restrict__ emb) {
    int i = blockIdx.x * 256 + threadIdx.x;    // 76*256 = HP*64 exact
    int k = i >> 6;
    g_h[0][i] = 0.0f;
    g_h[1][i] = 0.0f;
    g_xT[i] = (k < H_SZ) ? fmaxf(emb[k], 0.0f) : 0.0f;
    if (i == 0) g_bar = 0u;
}

// ---------------- gather encoder embeddings (+ zero pads) ----------------
__global__ void k_gather_enc(const int* __restrict__ input, const float* __restrict__ emb) {
    __shared__ int ids[B_SZ];
    int t = blockIdx.x, tid = threadIdx.x;
    if (tid < B_SZ) ids[tid] = input[t * B_SZ + tid];
    __syncthreads();
    for (int i = tid; i < B_SZ * H_SZ; i += 256) {
        int b = i / H_SZ, k = i - b * H_SZ;
        g_xT_all[((size_t)t * HP + k) * B_SZ + b] = emb[(size_t)ids[b] * H_SZ + k];
    }
    g_xT_all[((size_t)t * HP + H_SZ) * B_SZ + tid] = 0.0f;   // pads k=300..303
}

// ---------------- encoder: ALL 64 steps, one persistent kernel ------------
// grid 100 (3 n/block, all co-resident), block 512. Weights staged ONCE.
// Grid-wide barrier per step via monotonic counter (reset by k_init).
__global__ __launch_bounds__(512) void k_enc_all(
    const float* __restrict__ W_ih, const float* __restrict__ W_hh,
    const float* __restrict__ b_ih, const float* __restrict__ b_hh)
{
    __shared__ __align__(16) float Ws[18][HP];   // 21888 B, persists all steps
    __shared__ __align__(16) ull Red[8 * 9 * 32];// 18432 B, half-phase reduce

    int tid = threadIdx.x;
    int n0 = blockIdx.x * 3;
    int w = tid >> 5, lane = tid & 31;

    for (int i = tid; i < 18 * 75; i += 512) {
        int row = i / 75, q = i - row * 75;
        int rr = (row < 9) ? row : row - 9;
        int g = rr / 3, nl = rr - g * 3;
        const float* src = ((row < 9) ? W_ih : W_hh) + (size_t)(g * H_SZ + n0 + nl) * H_SZ;
        *(float4*)&Ws[row][q * 4] = *(const float4*)(src + q * 4);
    }
    if (tid < 18) { float4 z = {0.f, 0.f, 0.f, 0.f}; *(float4*)&Ws[tid][300] = z; }

    float bi_r = 0, bi_z = 0, bi_n = 0, bh_r = 0, bh_z = 0, bh_n = 0;
    int nl192 = 0, b192 = 0, n192 = 0;
    if (tid < 192) {
        nl192 = tid >> 6; b192 = tid & 63; n192 = n0 + nl192;
        bi_r = b_ih[n192]; bi_z = b_ih[H_SZ + n192]; bi_n = b_ih[2 * H_SZ + n192];
        bh_r = b_hh[n192]; bh_z = b_hh[H_SZ + n192]; bh_n = b_hh[2 * H_SZ + n192];
    }
    __syncthreads();

    int ks = w * 19;
    for (int t = 0; t < L_SZ; t++) {
        const float* xp = g_xT_all + (size_t)t * HP * B_SZ;
        const float* hp = g_h[t & 1];
        float* ho = g_h[(t + 1) & 1];

        ull a[18];
#pragma unroll
        for (int r = 0; r < 18; r++) a[r] = 0ull;

#pragma unroll 4
        for (int k = ks; k < ks + 19; k++) {
            ull xq = *(const ull*)(xp + k * 64 + lane * 2);
            ull hq = *(const ull*)(hp + k * 64 + lane * 2);
#pragma unroll
            for (int r = 0; r < 9; r++) ffma2(a[r], pk2(Ws[r][k], Ws[r][k]), xq);
#pragma unroll
            for (int r = 9; r < 18; r++) ffma2(a[r], pk2(Ws[r][k], Ws[r][k]), hq);
        }

        // ---- phase 1: rows 0..8 (input-side gates) ----
        if (w >= 8) {
#pragma unroll
            for (int r = 0; r < 9; r++) Red[((w - 8) * 9 + r) * 32 + lane] = a[r];
        }
        __syncthreads();
        if (w < 8) {
#pragma unroll
            for (int r = 0; r < 9; r++) {
                ull o = Red[(w * 9 + r) * 32 + lane];
                float2 pa = upk2(a[r]), po = upk2(o);
                Red[(w * 9 + r) * 32 + lane] = pk2(pa.x + po.x, pa.y + po.y);
            }
        }
        __syncthreads();
        float sir = 0, siz = 0, sin_ = 0;
        if (tid < 192) {
            const float* Rf = (const float*)Red;
#pragma unroll
            for (int p2 = 0; p2 < 8; p2++) {
                sir  += Rf[(p2 * 9 + nl192) * 64 + b192];
                siz  += Rf[(p2 * 9 + 3 + nl192) * 64 + b192];
                sin_ += Rf[(p2 * 9 + 6 + nl192) * 64 + b192];
            }
        }
        __syncthreads();

        // ---- phase 2: rows 9..17 (hidden-side gates) ----
        if (w >= 8) {
#pragma unroll
            for (int r = 0; r < 9; r++) Red[((w - 8) * 9 + r) * 32 + lane] = a[9 + r];
        }
        __syncthreads();
        if (w < 8) {
#pragma unroll
            for (int r = 0; r < 9; r++) {
                ull o = Red[(w * 9 + r) * 32 + lane];
                float2 pa = upk2(a[9 + r]), po = upk2(o);
                Red[(w * 9 + r) * 32 + lane] = pk2(pa.x + po.x, pa.y + po.y);
            }
        }
        __syncthreads();
        if (tid < 192) {
            const float* Rf = (const float*)Red;
            float shr = 0, shz = 0, shn = 0;
#pragma unroll
            for (int p2 = 0; p2 < 8; p2++) {
                shr += Rf[(p2 * 9 + nl192) * 64 + b192];
                shz += Rf[(p2 * 9 + 3 + nl192) * 64 + b192];
                shn += Rf[(p2 * 9 + 6 + nl192) * 64 + b192];
            }
            float r = sigd(sir + bi_r + shr + bh_r);
            float z = sigd(siz + bi_z + shz + bh_z);
            float nn = tanhd(sin_ + bi_n + r * (shn + bh_n));
            float hold = hp[n192 * 64 + b192];
            ho[n192 * 64 + b192] = (1.0f - z) * nn + z * hold;
            __threadfence();
        }
        __syncthreads();
        if (tid == 0) {
            atomicAdd(&g_bar, 1u);
            unsigned target = (unsigned)(t + 1) * (unsigned)ENC_GRID;
            while (atomicAdd(&g_bar, 0u) < target) { }
        }
        __syncthreads();
        __threadfence();
    }
}

// ---------------- decoder GRU step (same as R5) --------------------------
__global__ __launch_bounds__(512) void k_gru(
    const float* __restrict__ W_ih, const float* __restrict__ W_hh,
    const float* __restrict__ b_ih, const float* __restrict__ b_hh,
    int hin, int hout)
{
    __shared__ __align__(16) char smraw[36864];
    float (*Ws)[HP] = (float(*)[HP])smraw;    // [18][304] during main loop
    ull* Red = (ull*)smraw;                   // [8][18][32] ull after (union)

    int tid = threadIdx.x;
    int n0 = blockIdx.x * 3;
    int w = tid >> 5, lane = tid & 31;

    for (int i = tid; i < 18 * 75; i += 512) {
        int row = i / 75, q = i - row * 75;
        int rr = (row < 9) ? row : row - 9;
        int g = rr / 3, nl = rr - g * 3;
        const float* src = ((row < 9) ? W_ih : W_hh) + (size_t)(g * H_SZ + n0 + nl) * H_SZ;
        *(float4*)&Ws[row][q * 4] = *(const float4*)(src + q * 4);
    }
    if (tid < 18) { float4 z = {0.f, 0.f, 0.f, 0.f}; *(float4*)&Ws[tid][300] = z; }
    __syncthreads();

    const float* xp = g_xT;
    const float* hp = g_h[hin];
    int ks = w * 19;

    ull a[18];
#pragma unroll
    for (int r = 0; r < 18; r++) a[r] = 0ull;

#pragma unroll 4
    for (int k = ks; k < ks + 19; k++) {
        ull xq = *(const ull*)(xp + k * 64 + lane * 2);
        ull hq = *(const ull*)(hp + k * 64 + lane * 2);
#pragma unroll
        for (int r = 0; r < 9; r++) ffma2(a[r], pk2(Ws[r][k], Ws[r][k]), xq);
#pragma unroll
        for (int r = 9; r < 18; r++) ffma2(a[r], pk2(Ws[r][k], Ws[r][k]), hq);
    }
    __syncthreads();

    if (w >= 8) {
#pragma unroll
        for (int r = 0; r < 18; r++) Red[((w - 8) * 18 + r) * 32 + lane] = a[r];
    }
    __syncthreads();
    if (w < 8) {
#pragma unroll
        for (int r = 0; r < 18; r++) {
            ull o = Red[(w * 18 + r) * 32 + lane];
            float2 pa = upk2(a[r]), po = upk2(o);
            Red[(w * 18 + r) * 32 + lane] = pk2(pa.x + po.x, pa.y + po.y);
        }
    }
    __syncthreads();

    if (tid < 192) {
        int nl = tid >> 6, b = tid & 63;
        const float* Redf = (const float*)Red;
        float sir = 0, siz = 0, sin_ = 0, shr = 0, shz = 0, shn = 0;
#pragma unroll
        for (int s2 = 0; s2 < 8; s2++) {
            const float* base = Redf + s2 * 1152;
            sir  += base[nl * 64 + b];
            siz  += base[(3 + nl) * 64 + b];
            sin_ += base[(6 + nl) * 64 + b];
            shr  += base[(9 + nl) * 64 + b];
            shz  += base[(12 + nl) * 64 + b];
            shn  += base[(15 + nl) * 64 + b];
        }
        int n = n0 + nl;
        float r = sigd(sir + b_ih[n] + shr + b_hh[n]);
        float z = sigd(siz + b_ih[H_SZ + n] + shz + b_hh[H_SZ + n]);
        float nn = tanhd(sin_ + b_ih[2 * H_SZ + n] + r * (shn + b_hh[2 * H_SZ + n]));
        float hold = hp[n * 64 + b];
        g_h[hout][n * 64 + b] = (1.0f - z) * nn + z * hold;
    }
}

// ---------------- logits GEMM + fused per-block argmax -------------------
// grid 391, block 128 (R5 structure). vy = tid>>3 (16 groups x 16 rows),
// bx = tid&7 (8 batches). Change vs R5: W float4 loaded ONCE per kk4 per iv,
// feeding all 4 accumulators (h vectors hoisted).
__global__ __launch_bounds__(128) void k_logits(
    int hin, const float* __restrict__ W, const float* __restrict__ bias)
{
    __shared__ __align__(16) char sm[30208];
    float* Wt = (float*)sm;               // 256 rows x 24 floats + 16B skew /8 rows
    float* hs = (float*)(sm + 25088);     // [20][64]
    ull*   red = (ull*)sm;                // [16][64] after compute (union)

    int tid = threadIdx.x, blk = blockIdx.x;
    int v0 = blk * 256;
    int vy = tid >> 3, bx = tid & 7;
    const float* hT = g_h[hin];

    ull acc[16][4];
#pragma unroll
    for (int i = 0; i < 16; i++)
#pragma unroll
        for (int j = 0; j < 4; j++) acc[i][j] = 0ull;

    for (int c = 0; c < NCHUNK; c++) {    // 15 chunks of 20
        int k0 = c * KCH;
        for (int i = tid; i < 1280; i += 128) {
            int vl = i / 5, q = i - vl * 5;
            int rv = v0 + vl; if (rv > V_SZ - 1) rv = V_SZ - 1;
            unsigned dst = s2u(Wt + vl * 24 + (vl >> 3) * 4 + q * 4);
            CP16(dst, W + (size_t)rv * H_SZ + k0 + q * 4);
        }
        const float* hb = hT + k0 * 64;
        for (int i = tid; i < 320; i += 128) CP16(s2u(hs + i * 4), hb + i * 4);
        asm volatile("cp.async.commit_group;");
        asm volatile("cp.async.wait_group 0;");
        __syncthreads();

#pragma unroll
        for (int kk = 0; kk < KCH; kk += 4) {
            ulonglong2 hA0 = *(const ulonglong2*)(hs + (kk + 0) * 64 + bx * 8);
            ulonglong2 hB0 = *(const ulonglong2*)(hs + (kk + 0) * 64 + bx * 8 + 4);
            ulonglong2 hA1 = *(const ulonglong2*)(hs + (kk + 1) * 64 + bx * 8);
            ulonglong2 hB1 = *(const ulonglong2*)(hs + (kk + 1) * 64 + bx * 8 + 4);
            ulonglong2 hA2 = *(const ulonglong2*)(hs + (kk + 2) * 64 + bx * 8);
            ulonglong2 hB2 = *(const ulonglong2*)(hs + (kk + 2) * 64 + bx * 8 + 4);
            ulonglong2 hA3 = *(const ulonglong2*)(hs + (kk + 3) * 64 + bx * 8);
            ulonglong2 hB3 = *(const ulonglong2*)(hs + (kk + 3) * 64 + bx * 8 + 4);
#pragma unroll
            for (int iv = 0; iv < 16; iv++) {
                int vl = vy * 16 + iv;
                float4 wv = *(const float4*)(Wt + vl * 24 + (vl >> 3) * 4 + kk);
                ull w;
                w = pk2(wv.x, wv.x);
                ffma2(acc[iv][0], w, hA0.x); ffma2(acc[iv][1], w, hA0.y);
                ffma2(acc[iv][2], w, hB0.x); ffma2(acc[iv][3], w, hB0.y);
                w = pk2(wv.y, wv.y);
                ffma2(acc[iv][0], w, hA1.x); ffma2(acc[iv][1], w, hA1.y);
                ffma2(acc[iv][2], w, hB1.x); ffma2(acc[iv][3], w, hB1.y);
                w = pk2(wv.z, wv.z);
                ffma2(acc[iv][0], w, hA2.x); ffma2(acc[iv][1], w, hA2.y);
                ffma2(acc[iv][2], w, hB2.x); ffma2(acc[iv][3], w, hB2.y);
                w = pk2(wv.w, wv.w);
                ffma2(acc[iv][0], w, hA3.x); ffma2(acc[iv][1], w, hA3.y);
                ffma2(acc[iv][2], w, hB3.x); ffma2(acc[iv][3], w, hB3.y);
            }
        }
        __syncthreads();
    }

    // fused argmax: key = (ordered_float << 32) | ~v  (JAX first-index ties)
    ull lm[8];
#pragma unroll
    for (int j = 0; j < 8; j++) lm[j] = 0ull;
#pragma unroll
    for (int iv = 0; iv < 16; iv++) {
        int v = v0 + vy * 16 + iv;
        if (v < V_SZ) {
            float bj = bias[v];
            ull tg = (ull)(~(unsigned)v);
            float2 p0 = upk2(acc[iv][0]), p1 = upk2(acc[iv][1]);
            float2 p2 = upk2(acc[iv][2]), p3 = upk2(acc[iv][3]);
            lm[0] = umax64(lm[0], ((ull)ordf(p0.x + bj) << 32) | tg);
            lm[1] = umax64(lm[1], ((ull)ordf(p0.y + bj) << 32) | tg);
            lm[2] = umax64(lm[2], ((ull)ordf(p1.x + bj) << 32) | tg);
            lm[3] = umax64(lm[3], ((ull)ordf(p1.y + bj) << 32) | tg);
            lm[4] = umax64(lm[4], ((ull)ordf(p2.x + bj) << 32) | tg);
            lm[5] = umax64(lm[5], ((ull)ordf(p2.y + bj) << 32) | tg);
            lm[6] = umax64(lm[6], ((ull)ordf(p3.x + bj) << 32) | tg);
            lm[7] = umax64(lm[7], ((ull)ordf(p3.y + bj) << 32) | tg);
        }
    }
    __syncthreads();   // done with Wt/hs before red overlay
#pragma unroll
    for (int j = 0; j < 8; j++) red[vy * 64 + bx * 8 + j] = lm[j];
    __syncthreads();
    if (tid < B_SZ) {
        ull m = red[tid];
#pragma unroll
        for (int r = 1; r < 16; r++) m = umax64(m, red[r * 64 + tid]);
        g_part[blk * B_SZ + tid] = m;
    }
}

// ---------------- finalize ----------------
__global__ void k_finalize(const float* __restrict__ emb, float* __restrict__ out, int t) {
    __shared__ ull sred[256];
    __shared__ int sid;
    int b = blockIdx.x, tid = threadIdx.x;
    ull m = 0;
    for (int i = tid; i < NBLK_LOG; i += 256) m = umax64(m, g_part[i * B_SZ + b]);
    sred[tid] = m;
    __syncthreads();
    for (int s = 128; s > 0; s >>= 1) {
        if (tid < s) sred[tid] = umax64(sred[tid], sred[tid + s]);
        __syncthreads();
    }
    if (tid == 0) {
        unsigned id = ~(unsigned)(sred[0] & 0xffffffffull);
        sid = (int)id;
        out[t * B_SZ + b] = (float)id;
    }
    __syncthreads();
    int id = sid;
    for (int k = tid; k < H_SZ; k += 256)
        g_xT[k * 64 + b] = fmaxf(emb[(size_t)id * H_SZ + k], 0.0f);
}

// ---------------- launch ----------------
extern "C" void kernel_launch(void* const* d_in, const int* in_sizes, int n_in,
                              void* d_out, int out_size) {
    const int*   input = (const int*)d_in[0];
    const float* emb   = (const float*)d_in[1];
    const float* eWih  = (const float*)d_in[2];
    const float* eWhh  = (const float*)d_in[3];
    const float* ebih  = (const float*)d_in[4];
    const float* ebhh  = (const float*)d_in[5];
    const float* dWih  = (const float*)d_in[6];
    const float* dWhh  = (const float*)d_in[7];
    const float* dbih  = (const float*)d_in[8];
    const float* dbhh  = (const float*)d_in[9];
    const float* oW    = (const float*)d_in[10];
    const float* ob    = (const float*)d_in[11];
    float* out = (float*)d_out;

    k_init<<<76, 256>>>(emb);
    k_gather_enc<<<L_SZ, 256>>>(input, emb);

    // encoder: one persistent kernel, all 64 steps (ends with h in g_h[0])
    k_enc_all<<<ENC_GRID, 512>>>(eWih, eWhh, ebih, ebhh);

    // decoder
    int p = 0;
    for (int t = 0; t < L_SZ; t++) {
        k_gru<<<100, 512>>>(dWih, dWhh, dbih, dbhh, p, 1 - p);
        k_logits<<<NBLK_LOG, 128>>>(1 - p, oW, ob);
        k_finalize<<<B_SZ, 256>>>(emb, out, t);
        p = 1 - p;
    }
}

// round 11
// speedup vs baseline: 2.5008x; 1.2639x over previous
#include <cuda_runtime.h>
#include <cuda_bf16.h>
#include <mma.h>
#include <cstdint>
#include <math.h>

#define V_SZ 100000
#define H_SZ 300
#define HP   304
#define B_SZ 64
#define L_SZ 64
#define ENC_GRID 100
#define NTILE 782          // 782*128 = 100096 rows
#define KT 304             // MMA K padded: 19 k16-steps
#define CAP 16384
#define A_BYTES (128 * KT * 2)        // 77824
#define B_BYTES (B_SZ * KT * 2)       // 38912
#define BIAS_OFF (A_BYTES + B_BYTES)  // 116736
#define DSMEM_SZ (BIAS_OFF + 512)     // 117248

typedef unsigned long long ull;
using namespace nvcuda;

// ---------------- device scratch ----------------
__device__ __align__(16) float g_h[2][HP * B_SZ];
__device__ __align__(16) float g_xT[HP * B_SZ];
__device__ __align__(16) float g_xT_all[L_SZ * HP * B_SZ];
__device__ __align__(16) unsigned char g_Wb[(size_t)NTILE * A_BYTES];   // bf16 tiles
__device__ __align__(16) unsigned char g_hb[B_BYTES];                   // bf16 h^T
__device__ float g_approx[(size_t)NTILE * 128 * B_SZ];
__device__ ull g_part[NTILE * B_SZ];
__device__ float g_thrf[B_SZ];
__device__ int g_ccnt[B_SZ];
__device__ int g_cand[(size_t)B_SZ * CAP];
__device__ unsigned g_bar;

// ---------------- helpers ----------------
static __device__ __forceinline__ ull pk2(float lo, float hi) {
    ull r; asm("mov.b64 %0, {%1, %2};" : "=l"(r) : "f"(lo), "f"(hi)); return r;
}
static __device__ __forceinline__ void ffma2(ull& d, ull a, ull b) {
    asm("fma.rn.f32x2 %0, %1, %2, %0;" : "+l"(d) : "l"(a), "l"(b));
}
static __device__ __forceinline__ float2 upk2(ull v) {
    float2 r; asm("mov.b64 {%0, %1}, %2;" : "=f"(r.x), "=f"(r.y) : "l"(v)); return r;
}
static __device__ __forceinline__ unsigned ordf(float f) {
    unsigned u = __float_as_uint(f);
    return (u & 0x80000000u) ? ~u : (u | 0x80000000u);
}
static __device__ __forceinline__ float unordf(unsigned u) {
    return __uint_as_float((u & 0x80000000u) ? (u ^ 0x80000000u) : ~u);
}
static __device__ __forceinline__ ull umax64(ull a, ull b) { return a > b ? a : b; }
static __device__ __forceinline__ unsigned s2u(const void* p) {
    return (unsigned)__cvta_generic_to_shared(p);
}
static __device__ __forceinline__ unsigned pbf2(float lo, float hi) {
    unsigned r;
    asm("cvt.rn.bf16x2.f32 %0, %1, %2;" : "=r"(r) : "f"(hi), "f"(lo));
    return r;
}
#define CP16(dst, src) asm volatile("cp.async.cg.shared.global [%0], [%1], 16;" :: "r"(dst), "l"(src))

// ---------------- cheap double transcendentals ----------------
static __device__ __forceinline__ double dexp_(double x) {
    const double L2E = 1.4426950408889634074;
    const double LN2HI = 6.93147180369123816490e-01;
    const double LN2LO = 1.90821492927058770002e-10;
    int n = __double2int_rn(x * L2E);
    double nd = (double)n;
    double r = fma(-nd, LN2HI, x);
    r = fma(-nd, LN2LO, r);
    double p = 2.7557319223985893e-6;
    p = fma(p, r, 2.4801587301587302e-5);
    p = fma(p, r, 1.9841269841269841e-4);
    p = fma(p, r, 1.3888888888888889e-3);
    p = fma(p, r, 8.3333333333333333e-3);
    p = fma(p, r, 4.1666666666666667e-2);
    p = fma(p, r, 1.6666666666666667e-1);
    p = fma(p, r, 0.5);
    p = fma(p, r, 1.0);
    p = fma(p, r, 1.0);
    return p * __longlong_as_double((long long)((ull)(1023 + n) << 52));
}
static __device__ __forceinline__ float sigd(float x) {
    double xd = (double)fminf(fmaxf(x, -30.0f), 30.0f);
    double e = dexp_(-xd);
    double den = 1.0 + e;
    double r0 = (double)(1.0f / (float)den);
    r0 = r0 * fma(-den, r0, 2.0);
    return (float)r0;
}
static __device__ __forceinline__ float tanhd(float x) {
    double xd = (double)fminf(fmaxf(x, -30.0f), 30.0f);
    double e = dexp_(-2.0 * xd);
    double den = 1.0 + e;
    double r0 = (double)(1.0f / (float)den);
    r0 = r0 * fma(-den, r0, 2.0);
    return (float)fma(-2.0 * e, r0, 1.0);
}

// ---------------- init ----------------
__global__ void k_init(const float* __restrict__ emb) {
    int i = blockIdx.x * 256 + threadIdx.x;    // 76*256 = HP*64 exact
    int k = i >> 6;
    g_h[0][i] = 0.0f;
    g_h[1][i] = 0.0f;
    g_xT[i] = (k < H_SZ) ? fmaxf(emb[k], 0.0f) : 0.0f;
    if (i == 0) g_bar = 0u;
}

// ---------------- prep: W -> bf16 row-major tiles [128][KT] --------------
__global__ __launch_bounds__(256) void k_prep(const float* __restrict__ W) {
    int blk = blockIdx.x, tid = threadIdx.x;
    unsigned* dst = (unsigned*)(g_Wb + (size_t)blk * A_BYTES);
    for (int i = tid; i < 128 * (KT / 2); i += 256) {
        int l = i / (KT / 2), kw = i - l * (KT / 2);
        int k0 = kw * 2;
        int row = blk * 128 + l;
        float v0 = 0.f, v1 = 0.f;
        if (row < V_SZ) {
            if (k0 < H_SZ)     v0 = W[(size_t)row * H_SZ + k0];
            if (k0 + 1 < H_SZ) v1 = W[(size_t)row * H_SZ + k0 + 1];
        }
        dst[i] = pbf2(v0, v1);
    }
}

// ---------------- per-step: h -> bf16 h^T [n][KT] ----------------
__global__ void k_hprep(int hin) {
    int idx = blockIdx.x * 256 + threadIdx.x;          // grid 8 -> 2048 threads
    const float* hp = g_h[hin];
    unsigned* dst = (unsigned*)g_hb;
    for (int i = idx; i < B_SZ * (KT / 2); i += 2048) {
        int n = i / (KT / 2), kw = i - n * (KT / 2);
        int k0 = kw * 2;
        float v0 = (k0 < H_SZ) ? hp[k0 * 64 + n] : 0.f;
        float v1 = (k0 + 1 < H_SZ) ? hp[(k0 + 1) * 64 + n] : 0.f;
        dst[i] = pbf2(v0, v1);
    }
}

// ---------------- gather encoder embeddings ----------------
__global__ void k_gather_enc(const int* __restrict__ input, const float* __restrict__ emb) {
    __shared__ int ids[B_SZ];
    int t = blockIdx.x, tid = threadIdx.x;
    if (tid < B_SZ) ids[tid] = input[t * B_SZ + tid];
    __syncthreads();
    for (int i = tid; i < B_SZ * H_SZ; i += 256) {
        int b = i / H_SZ, k = i - b * H_SZ;
        g_xT_all[((size_t)t * HP + k) * B_SZ + b] = emb[(size_t)ids[b] * H_SZ + k];
    }
    g_xT_all[((size_t)t * HP + H_SZ) * B_SZ + tid] = 0.0f;
}

// ---------------- encoder: persistent, all 64 steps ----------------
__global__ __launch_bounds__(512) void k_enc_all(
    const float* __restrict__ W_ih, const float* __restrict__ W_hh,
    const float* __restrict__ b_ih, const float* __restrict__ b_hh)
{
    __shared__ __align__(16) float Ws[18][HP];
    __shared__ __align__(16) ull Red[8 * 9 * 32];

    int tid = threadIdx.x;
    int n0 = blockIdx.x * 3;
    int w = tid >> 5, lane = tid & 31;

    for (int i = tid; i < 18 * 75; i += 512) {
        int row = i / 75, q = i - row * 75;
        int rr = (row < 9) ? row : row - 9;
        int g = rr / 3, nl = rr - g * 3;
        const float* src = ((row < 9) ? W_ih : W_hh) + (size_t)(g * H_SZ + n0 + nl) * H_SZ;
        *(float4*)&Ws[row][q * 4] = *(const float4*)(src + q * 4);
    }
    if (tid < 18) { float4 z = {0.f, 0.f, 0.f, 0.f}; *(float4*)&Ws[tid][300] = z; }

    float bi_r = 0, bi_z = 0, bi_n = 0, bh_r = 0, bh_z = 0, bh_n = 0;
    int nl192 = 0, b192 = 0, n192 = 0;
    if (tid < 192) {
        nl192 = tid >> 6; b192 = tid & 63; n192 = n0 + nl192;
        bi_r = b_ih[n192]; bi_z = b_ih[H_SZ + n192]; bi_n = b_ih[2 * H_SZ + n192];
        bh_r = b_hh[n192]; bh_z = b_hh[H_SZ + n192]; bh_n = b_hh[2 * H_SZ + n192];
    }
    __syncthreads();

    int ks = w * 19;
    for (int t = 0; t < L_SZ; t++) {
        const float* xp = g_xT_all + (size_t)t * HP * B_SZ;
        const float* hp = g_h[t & 1];
        float* ho = g_h[(t + 1) & 1];

        ull a[18];
#pragma unroll
        for (int r = 0; r < 18; r++) a[r] = 0ull;

#pragma unroll 4
        for (int k = ks; k < ks + 19; k++) {
            ull xq = *(const ull*)(xp + k * 64 + lane * 2);
            ull hq = *(const ull*)(hp + k * 64 + lane * 2);
#pragma unroll
            for (int r = 0; r < 9; r++) ffma2(a[r], pk2(Ws[r][k], Ws[r][k]), xq);
#pragma unroll
            for (int r = 9; r < 18; r++) ffma2(a[r], pk2(Ws[r][k], Ws[r][k]), hq);
        }

        if (w >= 8) {
#pragma unroll
            for (int r = 0; r < 9; r++) Red[((w - 8) * 9 + r) * 32 + lane] = a[r];
        }
        __syncthreads();
        if (w < 8) {
#pragma unroll
            for (int r = 0; r < 9; r++) {
                ull o = Red[(w * 9 + r) * 32 + lane];
                float2 pa = upk2(a[r]), po = upk2(o);
                Red[(w * 9 + r) * 32 + lane] = pk2(pa.x + po.x, pa.y + po.y);
            }
        }
        __syncthreads();
        float sir = 0, siz = 0, sin_ = 0;
        if (tid < 192) {
            const float* Rf = (const float*)Red;
#pragma unroll
            for (int p2 = 0; p2 < 8; p2++) {
                sir  += Rf[(p2 * 9 + nl192) * 64 + b192];
                siz  += Rf[(p2 * 9 + 3 + nl192) * 64 + b192];
                sin_ += Rf[(p2 * 9 + 6 + nl192) * 64 + b192];
            }
        }
        __syncthreads();

        if (w >= 8) {
#pragma unroll
            for (int r = 0; r < 9; r++) Red[((w - 8) * 9 + r) * 32 + lane] = a[9 + r];
        }
        __syncthreads();
        if (w < 8) {
#pragma unroll
            for (int r = 0; r < 9; r++) {
                ull o = Red[(w * 9 + r) * 32 + lane];
                float2 pa = upk2(a[9 + r]), po = upk2(o);
                Red[(w * 9 + r) * 32 + lane] = pk2(pa.x + po.x, pa.y + po.y);
            }
        }
        __syncthreads();
        if (tid < 192) {
            const float* Rf = (const float*)Red;
            float shr = 0, shz = 0, shn = 0;
#pragma unroll
            for (int p2 = 0; p2 < 8; p2++) {
                shr += Rf[(p2 * 9 + nl192) * 64 + b192];
                shz += Rf[(p2 * 9 + 3 + nl192) * 64 + b192];
                shn += Rf[(p2 * 9 + 6 + nl192) * 64 + b192];
            }
            float r = sigd(sir + bi_r + shr + bh_r);
            float z = sigd(siz + bi_z + shz + bh_z);
            float nn = tanhd(sin_ + bi_n + r * (shn + bh_n));
            float hold = hp[n192 * 64 + b192];
            ho[n192 * 64 + b192] = (1.0f - z) * nn + z * hold;
            __threadfence();
        }
        __syncthreads();
        if (tid == 0) {
            atomicAdd(&g_bar, 1u);
            unsigned target = (unsigned)(t + 1) * (unsigned)ENC_GRID;
            while (atomicAdd(&g_bar, 0u) < target) { }
        }
        __syncthreads();
        __threadfence();
    }
}

// ---------------- decoder GRU step ----------------
__global__ __launch_bounds__(512) void k_gru(
    const float* __restrict__ W_ih, const float* __restrict__ W_hh,
    const float* __restrict__ b_ih, const float* __restrict__ b_hh,
    int hin, int hout)
{
    __shared__ __align__(16) char smraw[36864];
    float (*Ws)[HP] = (float(*)[HP])smraw;
    ull* Red = (ull*)smraw;

    int tid = threadIdx.x;
    int n0 = blockIdx.x * 3;
    int w = tid >> 5, lane = tid & 31;

    for (int i = tid; i < 18 * 75; i += 512) {
        int row = i / 75, q = i - row * 75;
        int rr = (row < 9) ? row : row - 9;
        int g = rr / 3, nl = rr - g * 3;
        const float* src = ((row < 9) ? W_ih : W_hh) + (size_t)(g * H_SZ + n0 + nl) * H_SZ;
        *(float4*)&Ws[row][q * 4] = *(const float4*)(src + q * 4);
    }
    if (tid < 18) { float4 z = {0.f, 0.f, 0.f, 0.f}; *(float4*)&Ws[tid][300] = z; }
    __syncthreads();

    const float* xp = g_xT;
    const float* hp = g_h[hin];
    int ks = w * 19;

    ull a[18];
#pragma unroll
    for (int r = 0; r < 18; r++) a[r] = 0ull;

#pragma unroll 4
    for (int k = ks; k < ks + 19; k++) {
        ull xq = *(const ull*)(xp + k * 64 + lane * 2);
        ull hq = *(const ull*)(hp + k * 64 + lane * 2);
#pragma unroll
        for (int r = 0; r < 9; r++) ffma2(a[r], pk2(Ws[r][k], Ws[r][k]), xq);
#pragma unroll
        for (int r = 9; r < 18; r++) ffma2(a[r], pk2(Ws[r][k], Ws[r][k]), hq);
    }
    __syncthreads();

    if (w >= 8) {
#pragma unroll
        for (int r = 0; r < 18; r++) Red[((w - 8) * 18 + r) * 32 + lane] = a[r];
    }
    __syncthreads();
    if (w < 8) {
#pragma unroll
        for (int r = 0; r < 18; r++) {
            ull o = Red[(w * 18 + r) * 32 + lane];
            float2 pa = upk2(a[r]), po = upk2(o);
            Red[(w * 18 + r) * 32 + lane] = pk2(pa.x + po.x, pa.y + po.y);
        }
    }
    __syncthreads();

    if (tid < 192) {
        int nl = tid >> 6, b = tid & 63;
        const float* Redf = (const float*)Red;
        float sir = 0, siz = 0, sin_ = 0, shr = 0, shz = 0, shn = 0;
#pragma unroll
        for (int s2 = 0; s2 < 8; s2++) {
            const float* base = Redf + s2 * 1152;
            sir  += base[nl * 64 + b];
            siz  += base[(3 + nl) * 64 + b];
            sin_ += base[(6 + nl) * 64 + b];
            shr  += base[(9 + nl) * 64 + b];
            shz  += base[(12 + nl) * 64 + b];
            shn  += base[(15 + nl) * 64 + b];
        }
        int n = n0 + nl;
        float r = sigd(sir + b_ih[n] + shr + b_hh[n]);
        float z = sigd(siz + b_ih[H_SZ + n] + shz + b_hh[H_SZ + n]);
        float nn = tanhd(sin_ + b_ih[2 * H_SZ + n] + r * (shn + b_hh[2 * H_SZ + n]));
        float hold = hp[n * 64 + b];
        g_h[hout][n * 64 + b] = (1.0f - z) * nn + z * hold;
    }
}

// ---------------- logits: WMMA bf16 approx + per-block max ---------------
__global__ __launch_bounds__(128) void k_mma(const float* __restrict__ bias) {
    extern __shared__ __align__(16) char smx[];
    int tid = threadIdx.x, blk = blockIdx.x;
    int w = tid >> 5;

    const unsigned char* srcA = g_Wb + (size_t)blk * A_BYTES;
    unsigned smA = s2u(smx), smB = smA + A_BYTES;
    for (int i = tid; i < A_BYTES / 16; i += 128) CP16(smA + i * 16, srcA + i * 16);
    for (int i = tid; i < B_BYTES / 16; i += 128) CP16(smB + i * 16, g_hb + i * 16);
    {
        int row = blk * 128 + tid;
        ((float*)(smx + BIAS_OFF))[tid] = (row < V_SZ) ? bias[row] : 0.f;
    }
    asm volatile("cp.async.commit_group;");
    asm volatile("cp.async.wait_group 0;");
    __syncthreads();

    const __nv_bfloat16* Af = (const __nv_bfloat16*)smx;
    const __nv_bfloat16* Bf = (const __nv_bfloat16*)(smx + A_BYTES);

    wmma::fragment<wmma::accumulator, 16, 16, 16, float> cfr[2][4];
#pragma unroll
    for (int mi = 0; mi < 2; mi++)
#pragma unroll
        for (int ni = 0; ni < 4; ni++) wmma::fill_fragment(cfr[mi][ni], 0.0f);

    for (int ks = 0; ks < KT / 16; ks++) {     // 19 k-steps
        wmma::fragment<wmma::matrix_a, 16, 16, 16, __nv_bfloat16, wmma::row_major> af0, af1;
        wmma::load_matrix_sync(af0, Af + (w * 32) * KT + ks * 16, KT);
        wmma::load_matrix_sync(af1, Af + (w * 32 + 16) * KT + ks * 16, KT);
#pragma unroll
        for (int ni = 0; ni < 4; ni++) {
            wmma::fragment<wmma::matrix_b, 16, 16, 16, __nv_bfloat16, wmma::col_major> bf;
            wmma::load_matrix_sync(bf, Bf + (ni * 16) * KT + ks * 16, KT);
            wmma::mma_sync(cfr[0][ni], af0, bf, cfr[0][ni]);
            wmma::mma_sync(cfr[1][ni], af1, bf, cfr[1][ni]);
        }
    }
    __syncthreads();

    float* sap = (float*)smx;                  // [128][64] overlay on A region
#pragma unroll
    for (int mi = 0; mi < 2; mi++)
#pragma unroll
        for (int ni = 0; ni < 4; ni++)
            wmma::store_matrix_sync(sap + (w * 32 + mi * 16) * 64 + ni * 16,
                                    cfr[mi][ni], 64, wmma::mem_row_major);
    __syncthreads();

    const float* sb = (const float*)(smx + BIAS_OFF);
    float4* s4 = (float4*)sap;
    float4* gdst = (float4*)(g_approx + (size_t)blk * 128 * 64);
#pragma unroll
    for (int j = 0; j < 16; j++) {
        int idx = j * 128 + tid;
        int r = idx >> 4;
        float4 v = s4[idx];
        float bb = sb[r];
        bool ok = (blk * 128 + r) < V_SZ;
        v.x = ok ? (v.x + bb) : -1e30f;
        v.y = ok ? (v.y + bb) : -1e30f;
        v.z = ok ? (v.z + bb) : -1e30f;
        v.w = ok ? (v.w + bb) : -1e30f;
        s4[idx] = v;
        gdst[idx] = v;
    }
    __syncthreads();

    if (tid < 64) {
        ull m = 0;
        for (int r = 0; r < 128; r++) {
            float v = sap[r * 64 + tid];
            m = umax64(m, ((ull)ordf(v) << 32) | (ull)(~(unsigned)(blk * 128 + r)));
        }
        g_part[blk * 64 + tid] = m;
    }
}

// ---------------- threshold: global max + ADAPTIVE margin per batch ------
// margin = 3e-4 * ||h||_1 + 1.5e-3  (rigorous bf16 bound 2.26e-4*||h||_1 + slack)
__global__ void k_thresh(int hin) {
    __shared__ ull sred[512];
    __shared__ float ssum[512];
    int tid = threadIdx.x;
    int s = tid >> 6, b = tid & 63;
    ull m = 0;
    for (int i = s; i < NTILE; i += 8) m = umax64(m, g_part[i * 64 + b]);
    float l1 = 0.f;
    const float* hp = g_h[hin];
    for (int k = s; k < H_SZ; k += 8) l1 += fabsf(hp[k * 64 + b]);
    sred[tid] = m; ssum[tid] = l1;
    __syncthreads();
    if (tid < 256) { sred[tid] = umax64(sred[tid], sred[tid + 256]); ssum[tid] += ssum[tid + 256]; }
    __syncthreads();
    if (tid < 128) { sred[tid] = umax64(sred[tid], sred[tid + 128]); ssum[tid] += ssum[tid + 128]; }
    __syncthreads();
    if (tid < 64) {
        ull mm = umax64(sred[tid], sred[tid + 64]);
        float l1t = ssum[tid] + ssum[tid + 64];
        float margin = 3.0e-4f * l1t + 1.5e-3f;
        g_thrf[tid] = unordf((unsigned)(mm >> 32)) - margin;
        g_ccnt[tid] = 0;
    }
}

// ---------------- select candidates ----------------
__global__ __launch_bounds__(128) void k_select() {
    __shared__ float sthr[64];
    int tid = threadIdx.x, blk = blockIdx.x;
    if (tid < 64) sthr[tid] = g_thrf[tid];
    __syncthreads();
    const float* ap = g_approx + (size_t)blk * 128 * 64;
    int base_row = blk * 128;
#pragma unroll 8
    for (int i = 0; i < 64; i++) {
        int f = i * 128 + tid;
        float v = ap[f];
        int c = f & 63;
        if (v >= sthr[c]) {
            int pos = atomicAdd(&g_ccnt[c], 1);
            if (pos < CAP) g_cand[(size_t)c * CAP + pos] = base_row + (f >> 6);
        }
    }
}

// ---------------- rescore exact + finalize (overflow-safe) ---------------
__global__ __launch_bounds__(256) void k_rescore(
    const float* __restrict__ W, const float* __restrict__ bias,
    const float* __restrict__ emb, float* __restrict__ out, int t, int hin)
{
    __shared__ float hsh[H_SZ];
    __shared__ ull wbest[8];
    __shared__ int sid;
    int b = blockIdx.x, tid = threadIdx.x, wid = tid >> 5, lane = tid & 31;
    for (int k = tid; k < H_SZ; k += 256) hsh[k] = g_h[hin][k * 64 + b];
    if (tid < 8) wbest[tid] = 0ull;
    __syncthreads();
    int n = g_ccnt[b];
    ull best = 0;
    if (n <= CAP) {
        for (int ci = wid; ci < n; ci += 8) {
            int r = g_cand[(size_t)b * CAP + ci];
            const float* wr = W + (size_t)r * H_SZ;
            float s = 0.f;
            for (int k = lane; k < H_SZ; k += 32) s = fmaf(wr[k], hsh[k], s);
#pragma unroll
            for (int o = 16; o; o >>= 1) s += __shfl_xor_sync(0xffffffffu, s, o);
            if (lane == 0) {
                float v = s + bias[r];
                best = umax64(best, ((ull)ordf(v) << 32) | (ull)(~(unsigned)r));
            }
        }
    } else {
        // last-resort fallback: exact scan of ALL rows for this batch
        for (int r = wid; r < V_SZ; r += 8) {
            const float* wr = W + (size_t)r * H_SZ;
            float s = 0.f;
            for (int k = lane; k < H_SZ; k += 32) s = fmaf(wr[k], hsh[k], s);
#pragma unroll
            for (int o = 16; o; o >>= 1) s += __shfl_xor_sync(0xffffffffu, s, o);
            if (lane == 0) {
                float v = s + bias[r];
                best = umax64(best, ((ull)ordf(v) << 32) | (ull)(~(unsigned)r));
            }
        }
    }
    if (lane == 0) wbest[wid] = umax64(wbest[wid], best);
    __syncthreads();
    if (tid == 0) {
        ull m = 0;
#pragma unroll
        for (int i = 0; i < 8; i++) m = umax64(m, wbest[i]);
        unsigned id = ~(unsigned)(m & 0xffffffffull);
        sid = (int)id;
        out[t * B_SZ + b] = (float)id;
    }
    __syncthreads();
    int id = sid;
    for (int k = tid; k < H_SZ; k += 256)
        g_xT[k * 64 + b] = fmaxf(emb[(size_t)id * H_SZ + k], 0.0f);
}

// ---------------- launch ----------------
extern "C" void kernel_launch(void* const* d_in, const int* in_sizes, int n_in,
                              void* d_out, int out_size) {
    const int*   input = (const int*)d_in[0];
    const float* emb   = (const float*)d_in[1];
    const float* eWih  = (const float*)d_in[2];
    const float* eWhh  = (const float*)d_in[3];
    const float* ebih  = (const float*)d_in[4];
    const float* ebhh  = (const float*)d_in[5];
    const float* dWih  = (const float*)d_in[6];
    const float* dWhh  = (const float*)d_in[7];
    const float* dbih  = (const float*)d_in[8];
    const float* dbhh  = (const float*)d_in[9];
    const float* oW    = (const float*)d_in[10];
    const float* ob    = (const float*)d_in[11];
    float* out = (float*)d_out;

    cudaFuncSetAttribute(k_mma, cudaFuncAttributeMaxDynamicSharedMemorySize, DSMEM_SZ);

    k_init<<<76, 256>>>(emb);
    k_prep<<<NTILE, 256>>>(oW);
    k_gather_enc<<<L_SZ, 256>>>(input, emb);
    k_enc_all<<<ENC_GRID, 512>>>(eWih, eWhh, ebih, ebhh);

    int p = 0;
    for (int t = 0; t < L_SZ; t++) {
        k_gru<<<100, 512>>>(dWih, dWhh, dbih, dbhh, p, 1 - p);
        k_hprep<<<8, 256>>>(1 - p);
        k_mma<<<NTILE, 128, DSMEM_SZ>>>(ob);
        k_thresh<<<1, 512>>>(1 - p);
        k_select<<<NTILE, 128>>>();
        k_rescore<<<B_SZ, 256>>>(oW, ob, emb, out, t, 1 - p);
        p = 1 - p;
    }
}

// round 12
// speedup vs baseline: 2.8637x; 1.1451x over previous
#include <cuda_runtime.h>
#include <cuda_bf16.h>
#include <mma.h>
#include <cstdint>
#include <math.h>

#define V_SZ 100000
#define H_SZ 300
#define HP   304
#define B_SZ 64
#define L_SZ 64
#define ENC_GRID 100
#define NTILE 782          // 782*128 = 100096 rows
#define KT 304             // MMA K padded: 19 k16-steps
#define CAP 16384
#define A_BYTES (128 * KT * 2)        // 77824
#define B_BYTES (B_SZ * KT * 2)       // 38912
#define BIAS_OFF (A_BYTES + B_BYTES)  // 116736
#define DSMEM_SZ (BIAS_OFF + 512)     // 117248

typedef unsigned long long ull;
using namespace nvcuda;

// ---------------- device scratch ----------------
__device__ __align__(16) float g_h[2][HP * B_SZ];
__device__ __align__(16) float g_xT[HP * B_SZ];
__device__ __align__(16) float g_xT_all[L_SZ * HP * B_SZ];
__device__ __align__(16) unsigned char g_Wb[(size_t)NTILE * A_BYTES];   // bf16 tiles
__device__ __align__(16) unsigned char g_hb[B_BYTES];                   // bf16 h^T
__device__ float g_approx[(size_t)NTILE * 128 * B_SZ];
__device__ ull g_part[NTILE * B_SZ];
__device__ float g_thrf[B_SZ];
__device__ int g_ccnt[B_SZ];
__device__ int g_cand[(size_t)B_SZ * CAP];
__device__ unsigned g_bar;

// ---------------- helpers ----------------
static __device__ __forceinline__ ull pk2(float lo, float hi) {
    ull r; asm("mov.b64 %0, {%1, %2};" : "=l"(r) : "f"(lo), "f"(hi)); return r;
}
static __device__ __forceinline__ void ffma2(ull& d, ull a, ull b) {
    asm("fma.rn.f32x2 %0, %1, %2, %0;" : "+l"(d) : "l"(a), "l"(b));
}
static __device__ __forceinline__ float2 upk2(ull v) {
    float2 r; asm("mov.b64 {%0, %1}, %2;" : "=f"(r.x), "=f"(r.y) : "l"(v)); return r;
}
static __device__ __forceinline__ unsigned ordf(float f) {
    unsigned u = __float_as_uint(f);
    return (u & 0x80000000u) ? ~u : (u | 0x80000000u);
}
static __device__ __forceinline__ float unordf(unsigned u) {
    return __uint_as_float((u & 0x80000000u) ? (u ^ 0x80000000u) : ~u);
}
static __device__ __forceinline__ ull umax64(ull a, ull b) { return a > b ? a : b; }
static __device__ __forceinline__ unsigned s2u(const void* p) {
    return (unsigned)__cvta_generic_to_shared(p);
}
static __device__ __forceinline__ unsigned pbf2(float lo, float hi) {
    unsigned r;
    asm("cvt.rn.bf16x2.f32 %0, %1, %2;" : "=r"(r) : "f"(hi), "f"(lo));
    return r;
}
#define CP16(dst, src) asm volatile("cp.async.cg.shared.global [%0], [%1], 16;" :: "r"(dst), "l"(src))

// ---------------- cheap double transcendentals ----------------
static __device__ __forceinline__ double dexp_(double x) {
    const double L2E = 1.4426950408889634074;
    const double LN2HI = 6.93147180369123816490e-01;
    const double LN2LO = 1.90821492927058770002e-10;
    int n = __double2int_rn(x * L2E);
    double nd = (double)n;
    double r = fma(-nd, LN2HI, x);
    r = fma(-nd, LN2LO, r);
    double p = 2.7557319223985893e-6;
    p = fma(p, r, 2.4801587301587302e-5);
    p = fma(p, r, 1.9841269841269841e-4);
    p = fma(p, r, 1.3888888888888889e-3);
    p = fma(p, r, 8.3333333333333333e-3);
    p = fma(p, r, 4.1666666666666667e-2);
    p = fma(p, r, 1.6666666666666667e-1);
    p = fma(p, r, 0.5);
    p = fma(p, r, 1.0);
    p = fma(p, r, 1.0);
    return p * __longlong_as_double((long long)((ull)(1023 + n) << 52));
}
static __device__ __forceinline__ float sigd(float x) {
    double xd = (double)fminf(fmaxf(x, -30.0f), 30.0f);
    double e = dexp_(-xd);
    double den = 1.0 + e;
    double r0 = (double)(1.0f / (float)den);
    r0 = r0 * fma(-den, r0, 2.0);
    return (float)r0;
}
static __device__ __forceinline__ float tanhd(float x) {
    double xd = (double)fminf(fmaxf(x, -30.0f), 30.0f);
    double e = dexp_(-2.0 * xd);
    double den = 1.0 + e;
    double r0 = (double)(1.0f / (float)den);
    r0 = r0 * fma(-den, r0, 2.0);
    return (float)fma(-2.0 * e, r0, 1.0);
}

// ---------------- init ----------------
__global__ void k_init(const float* __restrict__ emb) {
    int i = blockIdx.x * 256 + threadIdx.x;    // 76*256 = HP*64 exact
    int k = i >> 6;
    g_h[0][i] = 0.0f;
    g_h[1][i] = 0.0f;
    g_xT[i] = (k < H_SZ) ? fmaxf(emb[k], 0.0f) : 0.0f;
    if (i == 0) g_bar = 0u;
    if (i < 128) {            // zero g_hb pads (cols 300..303, 64 rows)
        int b = i >> 1, pr = i & 1;
        ((unsigned*)g_hb)[(b * KT + 300) / 2 + pr] = 0u;
    }
}

// ---------------- prep: W -> bf16 row-major tiles [128][KT] --------------
__global__ __launch_bounds__(256) void k_prep(const float* __restrict__ W) {
    int blk = blockIdx.x, tid = threadIdx.x;
    unsigned* dst = (unsigned*)(g_Wb + (size_t)blk * A_BYTES);
    for (int i = tid; i < 128 * (KT / 2); i += 256) {
        int l = i / (KT / 2), kw = i - l * (KT / 2);
        int k0 = kw * 2;
        int row = blk * 128 + l;
        float v0 = 0.f, v1 = 0.f;
        if (row < V_SZ) {
            if (k0 < H_SZ)     v0 = W[(size_t)row * H_SZ + k0];
            if (k0 + 1 < H_SZ) v1 = W[(size_t)row * H_SZ + k0 + 1];
        }
        dst[i] = pbf2(v0, v1);
    }
}

// ---------------- per-step: h -> bf16 h^T (used once for t=0's GRU input path)
__global__ void k_hprep(int hin) {
    int idx = blockIdx.x * 256 + threadIdx.x;
    const float* hp = g_h[hin];
    unsigned* dst = (unsigned*)g_hb;
    for (int i = idx; i < B_SZ * (KT / 2); i += 2048) {
        int n = i / (KT / 2), kw = i - n * (KT / 2);
        int k0 = kw * 2;
        float v0 = (k0 < H_SZ) ? hp[k0 * 64 + n] : 0.f;
        float v1 = (k0 + 1 < H_SZ) ? hp[(k0 + 1) * 64 + n] : 0.f;
        dst[i] = pbf2(v0, v1);
    }
}

// ---------------- gather encoder embeddings ----------------
__global__ void k_gather_enc(const int* __restrict__ input, const float* __restrict__ emb) {
    __shared__ int ids[B_SZ];
    int t = blockIdx.x, tid = threadIdx.x;
    if (tid < B_SZ) ids[tid] = input[t * B_SZ + tid];
    __syncthreads();
    for (int i = tid; i < B_SZ * H_SZ; i += 256) {
        int b = i / H_SZ, k = i - b * H_SZ;
        g_xT_all[((size_t)t * HP + k) * B_SZ + b] = emb[(size_t)ids[b] * H_SZ + k];
    }
    g_xT_all[((size_t)t * HP + H_SZ) * B_SZ + tid] = 0.0f;
}

// ---------------- encoder: persistent, all 64 steps ----------------
__global__ __launch_bounds__(512) void k_enc_all(
    const float* __restrict__ W_ih, const float* __restrict__ W_hh,
    const float* __restrict__ b_ih, const float* __restrict__ b_hh)
{
    __shared__ __align__(16) float Ws[18][HP];
    __shared__ __align__(16) ull Red[8 * 9 * 32];

    int tid = threadIdx.x;
    int n0 = blockIdx.x * 3;
    int w = tid >> 5, lane = tid & 31;

    for (int i = tid; i < 18 * 75; i += 512) {
        int row = i / 75, q = i - row * 75;
        int rr = (row < 9) ? row : row - 9;
        int g = rr / 3, nl = rr - g * 3;
        const float* src = ((row < 9) ? W_ih : W_hh) + (size_t)(g * H_SZ + n0 + nl) * H_SZ;
        *(float4*)&Ws[row][q * 4] = *(const float4*)(src + q * 4);
    }
    if (tid < 18) { float4 z = {0.f, 0.f, 0.f, 0.f}; *(float4*)&Ws[tid][300] = z; }

    float bi_r = 0, bi_z = 0, bi_n = 0, bh_r = 0, bh_z = 0, bh_n = 0;
    int nl192 = 0, b192 = 0, n192 = 0;
    if (tid < 192) {
        nl192 = tid >> 6; b192 = tid & 63; n192 = n0 + nl192;
        bi_r = b_ih[n192]; bi_z = b_ih[H_SZ + n192]; bi_n = b_ih[2 * H_SZ + n192];
        bh_r = b_hh[n192]; bh_z = b_hh[H_SZ + n192]; bh_n = b_hh[2 * H_SZ + n192];
    }
    __syncthreads();

    int ks = w * 19;
    for (int t = 0; t < L_SZ; t++) {
        const float* xp = g_xT_all + (size_t)t * HP * B_SZ;
        const float* hp = g_h[t & 1];
        float* ho = g_h[(t + 1) & 1];

        ull a[18];
#pragma unroll
        for (int r = 0; r < 18; r++) a[r] = 0ull;

#pragma unroll 4
        for (int k = ks; k < ks + 19; k++) {
            ull xq = *(const ull*)(xp + k * 64 + lane * 2);
            ull hq = *(const ull*)(hp + k * 64 + lane * 2);
#pragma unroll
            for (int r = 0; r < 9; r++) ffma2(a[r], pk2(Ws[r][k], Ws[r][k]), xq);
#pragma unroll
            for (int r = 9; r < 18; r++) ffma2(a[r], pk2(Ws[r][k], Ws[r][k]), hq);
        }

        if (w >= 8) {
#pragma unroll
            for (int r = 0; r < 9; r++) Red[((w - 8) * 9 + r) * 32 + lane] = a[r];
        }
        __syncthreads();
        if (w < 8) {
#pragma unroll
            for (int r = 0; r < 9; r++) {
                ull o = Red[(w * 9 + r) * 32 + lane];
                float2 pa = upk2(a[r]), po = upk2(o);
                Red[(w * 9 + r) * 32 + lane] = pk2(pa.x + po.x, pa.y + po.y);
            }
        }
        __syncthreads();
        float sir = 0, siz = 0, sin_ = 0;
        if (tid < 192) {
            const float* Rf = (const float*)Red;
#pragma unroll
            for (int p2 = 0; p2 < 8; p2++) {
                sir  += Rf[(p2 * 9 + nl192) * 64 + b192];
                siz  += Rf[(p2 * 9 + 3 + nl192) * 64 + b192];
                sin_ += Rf[(p2 * 9 + 6 + nl192) * 64 + b192];
            }
        }
        __syncthreads();

        if (w >= 8) {
#pragma unroll
            for (int r = 0; r < 9; r++) Red[((w - 8) * 9 + r) * 32 + lane] = a[9 + r];
        }
        __syncthreads();
        if (w < 8) {
#pragma unroll
            for (int r = 0; r < 9; r++) {
                ull o = Red[(w * 9 + r) * 32 + lane];
                float2 pa = upk2(a[9 + r]), po = upk2(o);
                Red[(w * 9 + r) * 32 + lane] = pk2(pa.x + po.x, pa.y + po.y);
            }
        }
        __syncthreads();
        if (tid < 192) {
            const float* Rf = (const float*)Red;
            float shr = 0, shz = 0, shn = 0;
#pragma unroll
            for (int p2 = 0; p2 < 8; p2++) {
                shr += Rf[(p2 * 9 + nl192) * 64 + b192];
                shz += Rf[(p2 * 9 + 3 + nl192) * 64 + b192];
                shn += Rf[(p2 * 9 + 6 + nl192) * 64 + b192];
            }
            float r = sigd(sir + bi_r + shr + bh_r);
            float z = sigd(siz + bi_z + shz + bh_z);
            float nn = tanhd(sin_ + bi_n + r * (shn + bh_n));
            float hold = hp[n192 * 64 + b192];
            ho[n192 * 64 + b192] = (1.0f - z) * nn + z * hold;
            __threadfence();
        }
        __syncthreads();
        if (tid == 0) {
            atomicAdd(&g_bar, 1u);
            unsigned target = (unsigned)(t + 1) * (unsigned)ENC_GRID;
            unsigned v;
            do {
                asm volatile("ld.acquire.gpu.u32 %0, [%1];" : "=r"(v) : "l"(&g_bar));
            } while (v < target);
        }
        __syncthreads();
    }
}

// ---------------- decoder GRU step (+ fused bf16 h^T emit) ---------------
__global__ __launch_bounds__(512) void k_gru(
    const float* __restrict__ W_ih, const float* __restrict__ W_hh,
    const float* __restrict__ b_ih, const float* __restrict__ b_hh,
    int hin, int hout)
{
    __shared__ __align__(16) char smraw[36864];
    float (*Ws)[HP] = (float(*)[HP])smraw;
    ull* Red = (ull*)smraw;

    int tid = threadIdx.x;
    int n0 = blockIdx.x * 3;
    int w = tid >> 5, lane = tid & 31;

    for (int i = tid; i < 18 * 75; i += 512) {
        int row = i / 75, q = i - row * 75;
        int rr = (row < 9) ? row : row - 9;
        int g = rr / 3, nl = rr - g * 3;
        const float* src = ((row < 9) ? W_ih : W_hh) + (size_t)(g * H_SZ + n0 + nl) * H_SZ;
        *(float4*)&Ws[row][q * 4] = *(const float4*)(src + q * 4);
    }
    if (tid < 18) { float4 z = {0.f, 0.f, 0.f, 0.f}; *(float4*)&Ws[tid][300] = z; }
    __syncthreads();

    const float* xp = g_xT;
    const float* hp = g_h[hin];
    int ks = w * 19;

    ull a[18];
#pragma unroll
    for (int r = 0; r < 18; r++) a[r] = 0ull;

#pragma unroll 4
    for (int k = ks; k < ks + 19; k++) {
        ull xq = *(const ull*)(xp + k * 64 + lane * 2);
        ull hq = *(const ull*)(hp + k * 64 + lane * 2);
#pragma unroll
        for (int r = 0; r < 9; r++) ffma2(a[r], pk2(Ws[r][k], Ws[r][k]), xq);
#pragma unroll
        for (int r = 9; r < 18; r++) ffma2(a[r], pk2(Ws[r][k], Ws[r][k]), hq);
    }
    __syncthreads();

    if (w >= 8) {
#pragma unroll
        for (int r = 0; r < 18; r++) Red[((w - 8) * 18 + r) * 32 + lane] = a[r];
    }
    __syncthreads();
    if (w < 8) {
#pragma unroll
        for (int r = 0; r < 18; r++) {
            ull o = Red[(w * 18 + r) * 32 + lane];
            float2 pa = upk2(a[r]), po = upk2(o);
            Red[(w * 18 + r) * 32 + lane] = pk2(pa.x + po.x, pa.y + po.y);
        }
    }
    __syncthreads();

    if (tid < 192) {
        int nl = tid >> 6, b = tid & 63;
        const float* Redf = (const float*)Red;
        float sir = 0, siz = 0, sin_ = 0, shr = 0, shz = 0, shn = 0;
#pragma unroll
        for (int s2 = 0; s2 < 8; s2++) {
            const float* base = Redf + s2 * 1152;
            sir  += base[nl * 64 + b];
            siz  += base[(3 + nl) * 64 + b];
            sin_ += base[(6 + nl) * 64 + b];
            shr  += base[(9 + nl) * 64 + b];
            shz  += base[(12 + nl) * 64 + b];
            shn  += base[(15 + nl) * 64 + b];
        }
        int n = n0 + nl;
        float r = sigd(sir + b_ih[n] + shr + b_hh[n]);
        float z = sigd(siz + b_ih[H_SZ + n] + shz + b_hh[H_SZ + n]);
        float nn = tanhd(sin_ + b_ih[2 * H_SZ + n] + r * (shn + b_hh[2 * H_SZ + n]));
        float hold = hp[n * 64 + b];
        float hv = (1.0f - z) * nn + z * hold;
        g_h[hout][n * 64 + b] = hv;
        ((__nv_bfloat16*)g_hb)[b * KT + n] = __float2bfloat16(hv);   // fused h^T emit
    }
}

// ---------------- logits: WMMA bf16 approx + per-block max ---------------
__global__ __launch_bounds__(128) void k_mma(const float* __restrict__ bias) {
    extern __shared__ __align__(16) char smx[];
    int tid = threadIdx.x, blk = blockIdx.x;
    int w = tid >> 5;

    const unsigned char* srcA = g_Wb + (size_t)blk * A_BYTES;
    unsigned smA = s2u(smx), smB = smA + A_BYTES;
    for (int i = tid; i < A_BYTES / 16; i += 128) CP16(smA + i * 16, srcA + i * 16);
    for (int i = tid; i < B_BYTES / 16; i += 128) CP16(smB + i * 16, g_hb + i * 16);
    {
        int row = blk * 128 + tid;
        ((float*)(smx + BIAS_OFF))[tid] = (row < V_SZ) ? bias[row] : 0.f;
    }
    asm volatile("cp.async.commit_group;");
    asm volatile("cp.async.wait_group 0;");
    __syncthreads();

    const __nv_bfloat16* Af = (const __nv_bfloat16*)smx;
    const __nv_bfloat16* Bf = (const __nv_bfloat16*)(smx + A_BYTES);

    wmma::fragment<wmma::accumulator, 16, 16, 16, float> cfr[2][4];
#pragma unroll
    for (int mi = 0; mi < 2; mi++)
#pragma unroll
        for (int ni = 0; ni < 4; ni++) wmma::fill_fragment(cfr[mi][ni], 0.0f);

    for (int ks = 0; ks < KT / 16; ks++) {     // 19 k-steps
        wmma::fragment<wmma::matrix_a, 16, 16, 16, __nv_bfloat16, wmma::row_major> af0, af1;
        wmma::load_matrix_sync(af0, Af + (w * 32) * KT + ks * 16, KT);
        wmma::load_matrix_sync(af1, Af + (w * 32 + 16) * KT + ks * 16, KT);
#pragma unroll
        for (int ni = 0; ni < 4; ni++) {
            wmma::fragment<wmma::matrix_b, 16, 16, 16, __nv_bfloat16, wmma::col_major> bf;
            wmma::load_matrix_sync(bf, Bf + (ni * 16) * KT + ks * 16, KT);
            wmma::mma_sync(cfr[0][ni], af0, bf, cfr[0][ni]);
            wmma::mma_sync(cfr[1][ni], af1, bf, cfr[1][ni]);
        }
    }
    __syncthreads();

    float* sap = (float*)smx;                  // [128][64] overlay on A region
#pragma unroll
    for (int mi = 0; mi < 2; mi++)
#pragma unroll
        for (int ni = 0; ni < 4; ni++)
            wmma::store_matrix_sync(sap + (w * 32 + mi * 16) * 64 + ni * 16,
                                    cfr[mi][ni], 64, wmma::mem_row_major);
    __syncthreads();

    const float* sb = (const float*)(smx + BIAS_OFF);
    float4* s4 = (float4*)sap;
    float4* gdst = (float4*)(g_approx + (size_t)blk * 128 * 64);
#pragma unroll
    for (int j = 0; j < 16; j++) {
        int idx = j * 128 + tid;
        int r = idx >> 4;
        float4 v = s4[idx];
        float bb = sb[r];
        bool ok = (blk * 128 + r) < V_SZ;
        v.x = ok ? (v.x + bb) : -1e30f;
        v.y = ok ? (v.y + bb) : -1e30f;
        v.z = ok ? (v.z + bb) : -1e30f;
        v.w = ok ? (v.w + bb) : -1e30f;
        s4[idx] = v;
        gdst[idx] = v;
    }
    __syncthreads();

    if (tid < 64) {
        ull m = 0;
        for (int r = 0; r < 128; r++) {
            float v = sap[r * 64 + tid];
            m = umax64(m, ((ull)ordf(v) << 32) | (ull)(~(unsigned)(blk * 128 + r)));
        }
        g_part[blk * 64 + tid] = m;
    }
}

// ---------------- threshold: grid 64 (one block per batch) ---------------
// margin = 3e-4 * ||h||_1 + 1.5e-3  (rigorous bf16 bound 2.26e-4*||h||_1 + slack)
__global__ __launch_bounds__(256) void k_thresh(int hin) {
    __shared__ ull sred[256];
    __shared__ float ssum[256];
    int b = blockIdx.x, tid = threadIdx.x;
    ull m = 0;
    for (int i = tid; i < NTILE; i += 256) m = umax64(m, g_part[i * 64 + b]);
    float l1 = 0.f;
    const float* hp = g_h[hin];
    for (int k = tid; k < H_SZ; k += 256) l1 += fabsf(hp[k * 64 + b]);
    sred[tid] = m; ssum[tid] = l1;
    __syncthreads();
    for (int s = 128; s > 0; s >>= 1) {
        if (tid < s) { sred[tid] = umax64(sred[tid], sred[tid + s]); ssum[tid] += ssum[tid + s]; }
        __syncthreads();
    }
    if (tid == 0) {
        float margin = 3.0e-4f * ssum[0] + 1.5e-3f;
        g_thrf[b] = unordf((unsigned)(sred[0] >> 32)) - margin;
        g_ccnt[b] = 0;
    }
}

// ---------------- select candidates ----------------
__global__ __launch_bounds__(128) void k_select() {
    __shared__ float sthr[64];
    int tid = threadIdx.x, blk = blockIdx.x;
    if (tid < 64) sthr[tid] = g_thrf[tid];
    __syncthreads();
    const float* ap = g_approx + (size_t)blk * 128 * 64;
    int base_row = blk * 128;
#pragma unroll 8
    for (int i = 0; i < 64; i++) {
        int f = i * 128 + tid;
        float v = ap[f];
        int c = f & 63;
        if (v >= sthr[c]) {
            int pos = atomicAdd(&g_ccnt[c], 1);
            if (pos < CAP) g_cand[(size_t)c * CAP + pos] = base_row + (f >> 6);
        }
    }
}

// ---------------- rescore exact + finalize (overflow-safe) ---------------
__global__ __launch_bounds__(256) void k_rescore(
    const float* __restrict__ W, const float* __restrict__ bias,
    const float* __restrict__ emb, float* __restrict__ out, int t, int hin)
{
    __shared__ float hsh[H_SZ];
    __shared__ ull wbest[8];
    __shared__ int sid;
    int b = blockIdx.x, tid = threadIdx.x, wid = tid >> 5, lane = tid & 31;
    for (int k = tid; k < H_SZ; k += 256) hsh[k] = g_h[hin][k * 64 + b];
    if (tid < 8) wbest[tid] = 0ull;
    __syncthreads();
    int n = g_ccnt[b];
    ull best = 0;
    if (n <= CAP) {
        for (int ci = wid; ci < n; ci += 8) {
            int r = g_cand[(size_t)b * CAP + ci];
            const float* wr = W + (size_t)r * H_SZ;
            float s = 0.f;
            for (int k = lane; k < H_SZ; k += 32) s = fmaf(wr[k], hsh[k], s);
#pragma unroll
            for (int o = 16; o; o >>= 1) s += __shfl_xor_sync(0xffffffffu, s, o);
            if (lane == 0) {
                float v = s + bias[r];
                best = umax64(best, ((ull)ordf(v) << 32) | (ull)(~(unsigned)r));
            }
        }
    } else {
        for (int r = wid; r < V_SZ; r += 8) {
            const float* wr = W + (size_t)r * H_SZ;
            float s = 0.f;
            for (int k = lane; k < H_SZ; k += 32) s = fmaf(wr[k], hsh[k], s);
#pragma unroll
            for (int o = 16; o; o >>= 1) s += __shfl_xor_sync(0xffffffffu, s, o);
            if (lane == 0) {
                float v = s + bias[r];
                best = umax64(best, ((ull)ordf(v) << 32) | (ull)(~(unsigned)r));
            }
        }
    }
    if (lane == 0) wbest[wid] = umax64(wbest[wid], best);
    __syncthreads();
    if (tid == 0) {
        ull m = 0;
#pragma unroll
        for (int i = 0; i < 8; i++) m = umax64(m, wbest[i]);
        unsigned id = ~(unsigned)(m & 0xffffffffull);
        sid = (int)id;
        out[t * B_SZ + b] = (float)id;
    }
    __syncthreads();
    int id = sid;
    for (int k = tid; k < H_SZ; k += 256)
        g_xT[k * 64 + b] = fmaxf(emb[(size_t)id * H_SZ + k], 0.0f);
}

// ---------------- launch ----------------
extern "C" void kernel_launch(void* const* d_in, const int* in_sizes, int n_in,
                              void* d_out, int out_size) {
    const int*   input = (const int*)d_in[0];
    const float* emb   = (const float*)d_in[1];
    const float* eWih  = (const float*)d_in[2];
    const float* eWhh  = (const float*)d_in[3];
    const float* ebih  = (const float*)d_in[4];
    const float* ebhh  = (const float*)d_in[5];
    const float* dWih  = (const float*)d_in[6];
    const float* dWhh  = (const float*)d_in[7];
    const float* dbih  = (const float*)d_in[8];
    const float* dbhh  = (const float*)d_in[9];
    const float* oW    = (const float*)d_in[10];
    const float* ob    = (const float*)d_in[11];
    float* out = (float*)d_out;

    cudaFuncSetAttribute(k_mma, cudaFuncAttributeMaxDynamicSharedMemorySize, DSMEM_SZ);

    k_init<<<76, 256>>>(emb);
    k_prep<<<NTILE, 256>>>(oW);
    k_gather_enc<<<L_SZ, 256>>>(input, emb);
    k_enc_all<<<ENC_GRID, 512>>>(eWih, eWhh, ebih, ebhh);

    int p = 0;
    for (int t = 0; t < L_SZ; t++) {
        k_gru<<<100, 512>>>(dWih, dWhh, dbih, dbhh, p, 1 - p);   // also emits bf16 h^T
        k_mma<<<NTILE, 128, DSMEM_SZ>>>(ob);
        k_thresh<<<B_SZ, 256>>>(1 - p);
        k_select<<<NTILE, 128>>>();
        k_rescore<<<B_SZ, 256>>>(oW, ob, emb, out, t, 1 - p);
        p = 1 - p;
    }
}